// round 7
// baseline (speedup 1.0000x reference)
#include <cuda_runtime.h>
#include <cuda_bf16.h>

// Problem constants (from reference setup_inputs)
#define N_   64
#define C_   960
#define CS_  240
#define HW_  784            // 28*28
#define HW4_ 196            // 784/4 float4s per plane
#define PLANES_ (N_ * C_)   // 61440
#define TOTAL4_ (PLANES_ * HW4_)  // 12,042,240 float4s

// Scratch (allocation-free rule: __device__ globals)
__device__ float g_pooled[PLANES_];
__device__ float g_scale[PLANES_];

// ---------------------------------------------------------------------------
// Kernel 1: global average pool. One WARP per (n,c) plane; 8 planes per
// 256-thread block. Each lane issues 6-7 independent float4 loads (MLP>=6),
// then a shfl-only warp reduction. No smem, no __syncthreads.
// ---------------------------------------------------------------------------
__global__ __launch_bounds__(256) void pool_kernel(const float* __restrict__ x) {
    const int warp_in_blk = threadIdx.x >> 5;
    const int lane = threadIdx.x & 31;
    const int plane = blockIdx.x * 8 + warp_in_blk;   // exact: PLANES_/8 blocks

    const float4* __restrict__ p =
        reinterpret_cast<const float4*>(x) + (size_t)plane * HW4_;

    // 196 = 6*32 + 4 : lanes 0..3 take a 7th element
    float4 v0 = p[lane];
    float4 v1 = p[lane + 32];
    float4 v2 = p[lane + 64];
    float4 v3 = p[lane + 96];
    float4 v4 = p[lane + 128];
    float4 v5 = p[lane + 160];
    float sum = 0.0f;
    if (lane < 4) {
        float4 v6 = p[lane + 192];
        sum = (v6.x + v6.y) + (v6.z + v6.w);
    }
    sum += (v0.x + v0.y) + (v0.z + v0.w);
    sum += (v1.x + v1.y) + (v1.z + v1.w);
    sum += (v2.x + v2.y) + (v2.z + v2.w);
    sum += (v3.x + v3.y) + (v3.z + v3.w);
    sum += (v4.x + v4.y) + (v4.z + v4.w);
    sum += (v5.x + v5.y) + (v5.z + v5.w);

    #pragma unroll
    for (int off = 16; off > 0; off >>= 1)
        sum += __shfl_down_sync(0xFFFFFFFFu, sum, off);

    if (lane == 0)
        g_pooled[plane] = sum * (1.0f / (float)HW_);
}

// ---------------------------------------------------------------------------
// Kernel 2: fc1 + ReLU + fc2 + hardsigmoid. One block per batch index n.
// 256 threads. Tiny compute; weights (0.9+0.9 MB) stay hot in L2 across n.
// ---------------------------------------------------------------------------
__global__ __launch_bounds__(256) void fc_kernel(const float* __restrict__ w1,
                                                 const float* __restrict__ b1,
                                                 const float* __restrict__ w2,
                                                 const float* __restrict__ b2) {
    __shared__ float sp[C_];   // pooled row for this n
    __shared__ float sh[CS_];  // hidden activations

    const int n = blockIdx.x;
    for (int c = threadIdx.x; c < C_; c += 256)
        sp[c] = g_pooled[n * C_ + c];
    __syncthreads();

    // fc1: h[s] = relu(b1[s] + sum_c pooled[c] * w1[s,c]); threads 0..239
    if (threadIdx.x < CS_) {
        const float* __restrict__ wr = w1 + threadIdx.x * C_;
        float acc = b1[threadIdx.x];
        #pragma unroll 8
        for (int c = 0; c < C_; c++)
            acc = fmaf(sp[c], wr[c], acc);
        sh[threadIdx.x] = fmaxf(acc, 0.0f);
    }
    __syncthreads();

    // fc2 + hardsigmoid: scale[c] = sat((b2[c] + sum_s h[s]*w2[c,s] + 3)/6)
    for (int c = threadIdx.x; c < C_; c += 256) {
        const float* __restrict__ wr = w2 + c * CS_;
        float acc = b2[c];
        #pragma unroll 8
        for (int s = 0; s < CS_; s++)
            acc = fmaf(sh[s], wr[s], acc);
        g_scale[n * C_ + c] = __saturatef((acc + 3.0f) * (1.0f / 6.0f));
    }
}

// ---------------------------------------------------------------------------
// Kernel 3: broadcast-multiply. Flat layout over float4s. Inner group of 4:
// all address math first, then 8 independent loads (4x LDG.128 + 4x LDG.32
// scale), then FMUL, then 4 stores — maximizes front-batched MLP. Plane index
// via constant div (mul+shift); g_scale (245 KB) is L2-resident broadcast.
// ---------------------------------------------------------------------------
#define APPLY_BLOCKS (148 * 8)          // 1184 blocks, occ 8
#define APPLY_THREADS 256
#define APPLY_STRIDE (APPLY_BLOCKS * APPLY_THREADS)   // 303,104

__global__ __launch_bounds__(APPLY_THREADS) void apply_kernel(
    const float* __restrict__ x, float* __restrict__ out) {
    const float4* __restrict__ xi = reinterpret_cast<const float4*>(x);
    float4* __restrict__ xo = reinterpret_cast<float4*>(out);

    int i = blockIdx.x * APPLY_THREADS + threadIdx.x;

    // Main body: groups of 4 strided elements, loads front-batched.
    // TOTAL4_ / APPLY_STRIDE = 39.7 -> 9 full groups of 4 + tail.
    for (; i + 3 * APPLY_STRIDE < TOTAL4_; i += 4 * APPLY_STRIDE) {
        const int i0 = i;
        const int i1 = i + APPLY_STRIDE;
        const int i2 = i + 2 * APPLY_STRIDE;
        const int i3 = i + 3 * APPLY_STRIDE;
        // All index math before any load:
        const int p0 = i0 / HW4_;
        const int p1 = i1 / HW4_;
        const int p2 = i2 / HW4_;
        const int p3 = i3 / HW4_;
        // 8 independent loads:
        float4 v0 = xi[i0];
        float4 v1 = xi[i1];
        float4 v2 = xi[i2];
        float4 v3 = xi[i3];
        const float s0 = __ldg(&g_scale[p0]);
        const float s1 = __ldg(&g_scale[p1]);
        const float s2 = __ldg(&g_scale[p2]);
        const float s3 = __ldg(&g_scale[p3]);
        v0.x *= s0; v0.y *= s0; v0.z *= s0; v0.w *= s0;
        v1.x *= s1; v1.y *= s1; v1.z *= s1; v1.w *= s1;
        v2.x *= s2; v2.y *= s2; v2.z *= s2; v2.w *= s2;
        v3.x *= s3; v3.y *= s3; v3.z *= s3; v3.w *= s3;
        xo[i0] = v0;
        xo[i1] = v1;
        xo[i2] = v2;
        xo[i3] = v3;
    }
    // Tail
    for (; i < TOTAL4_; i += APPLY_STRIDE) {
        const float s = __ldg(&g_scale[i / HW4_]);
        float4 v = xi[i];
        v.x *= s; v.y *= s; v.z *= s; v.w *= s;
        xo[i] = v;
    }
}

// ---------------------------------------------------------------------------
// Launch: x, w1, b1, w2, b2 (metadata order), out fp32 [N,C,H,W]
// ---------------------------------------------------------------------------
extern "C" void kernel_launch(void* const* d_in, const int* in_sizes, int n_in,
                              void* d_out, int out_size) {
    const float* x  = (const float*)d_in[0];
    const float* w1 = (const float*)d_in[1];
    const float* b1 = (const float*)d_in[2];
    const float* w2 = (const float*)d_in[3];
    const float* b2 = (const float*)d_in[4];
    float* out = (float*)d_out;

    pool_kernel<<<PLANES_ / 8, 256>>>(x);
    fc_kernel<<<N_, 256>>>(w1, b1, w2, b2);
    apply_kernel<<<APPLY_BLOCKS, APPLY_THREADS>>>(x, out);
}

// round 15
// speedup vs baseline: 1.2370x; 1.2370x over previous
#include <cuda_runtime.h>
#include <cuda_bf16.h>

// Problem constants (from reference setup_inputs)
#define N_   64
#define C_   960
#define CS_  240
#define HW_  784            // 28*28
#define HW4_ 196            // 784/4 float4s per plane
#define PLANES_ (N_ * C_)   // 61440
#define TOTAL4_ (PLANES_ * HW4_)  // 12,042,240 float4s

// Scratch (allocation-free rule: __device__ globals)
__device__ float g_pooled[PLANES_];
__device__ float g_scale[PLANES_];

// ---------------------------------------------------------------------------
// Kernel 1: global average pool. One WARP per (n,c) plane; 8 planes per
// 256-thread block. MLP 6-7 independent float4 loads per lane, shfl reduce.
// Measured: 31.8us @ 77.9% DRAM. Unchanged.
// ---------------------------------------------------------------------------
__global__ __launch_bounds__(256) void pool_kernel(const float* __restrict__ x) {
    const int warp_in_blk = threadIdx.x >> 5;
    const int lane = threadIdx.x & 31;
    const int plane = blockIdx.x * 8 + warp_in_blk;

    const float4* __restrict__ p =
        reinterpret_cast<const float4*>(x) + (size_t)plane * HW4_;

    float4 v0 = p[lane];
    float4 v1 = p[lane + 32];
    float4 v2 = p[lane + 64];
    float4 v3 = p[lane + 96];
    float4 v4 = p[lane + 128];
    float4 v5 = p[lane + 160];
    float sum = 0.0f;
    if (lane < 4) {
        float4 v6 = p[lane + 192];
        sum = (v6.x + v6.y) + (v6.z + v6.w);
    }
    sum += (v0.x + v0.y) + (v0.z + v0.w);
    sum += (v1.x + v1.y) + (v1.z + v1.w);
    sum += (v2.x + v2.y) + (v2.z + v2.w);
    sum += (v3.x + v3.y) + (v3.z + v3.w);
    sum += (v4.x + v4.y) + (v4.z + v4.w);
    sum += (v5.x + v5.y) + (v5.z + v5.w);

    #pragma unroll
    for (int off = 16; off > 0; off >>= 1)
        sum += __shfl_down_sync(0xFFFFFFFFu, sum, off);

    if (lane == 0)
        g_pooled[plane] = sum * (1.0f / (float)HW_);
}

// ---------------------------------------------------------------------------
// Kernel 2 (R7 rewrite, unmeasured): fc1 + ReLU + fc2 + hardsigmoid,
// warp-cooperative. One block per n. A warp owns one output at a time; its
// 32 lanes stride ALONG the weight row (coalesced 128B lines), shfl-reduce.
// Old version: lanes on different rows -> 32 L1 wavefronts per LDG, ~190us.
// ---------------------------------------------------------------------------
__global__ __launch_bounds__(256) void fc_kernel(const float* __restrict__ w1,
                                                 const float* __restrict__ b1,
                                                 const float* __restrict__ w2,
                                                 const float* __restrict__ b2) {
    __shared__ float sp[C_];   // pooled row for this n
    __shared__ float sh[CS_];  // hidden activations

    const int n = blockIdx.x;
    const int wid = threadIdx.x >> 5;
    const int lane = threadIdx.x & 31;

    for (int c = threadIdx.x; c < C_; c += 256)
        sp[c] = g_pooled[n * C_ + c];
    __syncthreads();

    // fc1: 240 outputs; 8 warps x 30 outputs. Lanes stride along the row.
    for (int s = wid; s < CS_; s += 8) {
        const float* __restrict__ wr = w1 + s * C_;
        float acc = 0.0f;
        #pragma unroll 6
        for (int c = lane; c < C_; c += 32)    // 30 coalesced iterations
            acc = fmaf(sp[c], wr[c], acc);
        #pragma unroll
        for (int off = 16; off > 0; off >>= 1)
            acc += __shfl_down_sync(0xFFFFFFFFu, acc, off);
        if (lane == 0)
            sh[s] = fmaxf(acc + b1[s], 0.0f);
    }
    __syncthreads();

    // fc2: 960 outputs; 8 warps x 120 outputs. 240-length dots.
    for (int c = wid; c < C_; c += 8) {
        const float* __restrict__ wr = w2 + c * CS_;
        float acc = 0.0f;
        #pragma unroll
        for (int s = lane; s < CS_; s += 32)   // 7-8 coalesced iterations
            acc = fmaf(sh[s], wr[s], acc);
        #pragma unroll
        for (int off = 16; off > 0; off >>= 1)
            acc += __shfl_down_sync(0xFFFFFFFFu, acc, off);
        if (lane == 0)
            g_scale[n * C_ + c] = __saturatef((acc + b2[c] + 3.0f) * (1.0f / 6.0f));
    }
}

// ---------------------------------------------------------------------------
// Kernel 3: broadcast-multiply. Flat over float4s, x4 front-batched groups.
// __ldcs on x (no reuse after this read) and __stwt on out (never re-read)
// — streaming cache policy, keeps L2 lines from churning.
// ---------------------------------------------------------------------------
#define APPLY_BLOCKS (148 * 8)          // 1184 blocks
#define APPLY_THREADS 256
#define APPLY_STRIDE (APPLY_BLOCKS * APPLY_THREADS)   // 303,104

__global__ __launch_bounds__(APPLY_THREADS) void apply_kernel(
    const float* __restrict__ x, float* __restrict__ out) {
    const float4* __restrict__ xi = reinterpret_cast<const float4*>(x);
    float4* __restrict__ xo = reinterpret_cast<float4*>(out);

    int i = blockIdx.x * APPLY_THREADS + threadIdx.x;

    for (; i + 3 * APPLY_STRIDE < TOTAL4_; i += 4 * APPLY_STRIDE) {
        const int i0 = i;
        const int i1 = i + APPLY_STRIDE;
        const int i2 = i + 2 * APPLY_STRIDE;
        const int i3 = i + 3 * APPLY_STRIDE;
        const int p0 = i0 / HW4_;
        const int p1 = i1 / HW4_;
        const int p2 = i2 / HW4_;
        const int p3 = i3 / HW4_;
        float4 v0 = __ldcs(&xi[i0]);
        float4 v1 = __ldcs(&xi[i1]);
        float4 v2 = __ldcs(&xi[i2]);
        float4 v3 = __ldcs(&xi[i3]);
        const float s0 = __ldg(&g_scale[p0]);
        const float s1 = __ldg(&g_scale[p1]);
        const float s2 = __ldg(&g_scale[p2]);
        const float s3 = __ldg(&g_scale[p3]);
        v0.x *= s0; v0.y *= s0; v0.z *= s0; v0.w *= s0;
        v1.x *= s1; v1.y *= s1; v1.z *= s1; v1.w *= s1;
        v2.x *= s2; v2.y *= s2; v2.z *= s2; v2.w *= s2;
        v3.x *= s3; v3.y *= s3; v3.z *= s3; v3.w *= s3;
        __stwt(&xo[i0], v0);
        __stwt(&xo[i1], v1);
        __stwt(&xo[i2], v2);
        __stwt(&xo[i3], v3);
    }
    for (; i < TOTAL4_; i += APPLY_STRIDE) {
        const float s = __ldg(&g_scale[i / HW4_]);
        float4 v = __ldcs(&xi[i]);
        v.x *= s; v.y *= s; v.z *= s; v.w *= s;
        __stwt(&xo[i], v);
    }
}

// ---------------------------------------------------------------------------
// Launch: x, w1, b1, w2, b2 (metadata order), out fp32 [N,C,H,W]
// ---------------------------------------------------------------------------
extern "C" void kernel_launch(void* const* d_in, const int* in_sizes, int n_in,
                              void* d_out, int out_size) {
    const float* x  = (const float*)d_in[0];
    const float* w1 = (const float*)d_in[1];
    const float* b1 = (const float*)d_in[2];
    const float* w2 = (const float*)d_in[3];
    const float* b2 = (const float*)d_in[4];
    float* out = (float*)d_out;

    pool_kernel<<<PLANES_ / 8, 256>>>(x);
    fc_kernel<<<N_, 256>>>(w1, b1, w2, b2);
    apply_kernel<<<APPLY_BLOCKS, APPLY_THREADS>>>(x, out);
}